// round 10
// baseline (speedup 1.0000x reference)
#include <cuda_runtime.h>
#include <cuda_fp16.h>
#include <cstdint>

// ============================================================================
// LSTM cell via mma.sync fp16 single-pass (fp32 accum), fused LSTM epilogue.
// B=65536, Din=256, H=512 fixed.
// CTA: 128 batch x 128 cols (4 gates x 32 h). 8 warps (2M x 4N), warp 64x32.
// K pipeline: BK=64, 3-buffer cp.async ring, 12 stages, ONE sync per stage
// (load-before-compute: top-of-loop sync proves all warps finished stage s-1,
// which owns the same buffer stage s+2 overwrites).
// ============================================================================

#define BATCH 65536
#define DIN   256
#define HH    512
#define BM    128
#define BK    64
#define NSTAGE 12

// ---------------- device scratch --------------------------------------------
__device__ __half g_Xh[BATCH * DIN];
__device__ __half g_Hh[BATCH * HH];
__device__ __half g_Ut[4 * HH * DIN];   // [g][h][k] K-major
__device__ __half g_Wt[4 * HH * HH];
__device__ float  g_bias[4 * HH];        // bU + bW

// ---------------- helpers ----------------------------------------------------
__device__ __forceinline__ uint32_t smem_u32(const void* p) {
    uint32_t a;
    asm("{ .reg .u64 t; cvta.to.shared.u64 t, %1; cvt.u32.u64 %0, t; }"
        : "=r"(a) : "l"(p));
    return a;
}
#define SW128(off) ((off) ^ (((off) >> 3) & 0x70))

__device__ __forceinline__ void cp16(uint32_t dst, const void* src) {
    asm volatile("cp.async.cg.shared.global [%0], [%1], 16;\n" :: "r"(dst), "l"(src));
}
#define CP_COMMIT() asm volatile("cp.async.commit_group;\n" ::: "memory")
#define CP_WAIT1()  asm volatile("cp.async.wait_group 1;\n" ::: "memory")
#define CP_WAIT0()  asm volatile("cp.async.wait_group 0;\n" ::: "memory")

#define LDSM_X4(r0, r1, r2, r3, a)                                              \
    asm volatile("ldmatrix.sync.aligned.m8n8.x4.shared.b16 {%0,%1,%2,%3}, [%4];"\
        : "=r"(r0), "=r"(r1), "=r"(r2), "=r"(r3) : "r"(a))

__device__ __forceinline__ void mma16816(float* c, uint32_t a0, uint32_t a1,
                                         uint32_t a2, uint32_t a3,
                                         uint32_t b0, uint32_t b1) {
    asm volatile(
        "mma.sync.aligned.m16n8k16.row.col.f32.f16.f16.f32 "
        "{%0,%1,%2,%3}, {%4,%5,%6,%7}, {%8,%9}, {%0,%1,%2,%3};"
        : "+f"(c[0]), "+f"(c[1]), "+f"(c[2]), "+f"(c[3])
        : "r"(a0), "r"(a1), "r"(a2), "r"(a3), "r"(b0), "r"(b1));
}

// ---------------- SMEM layout ------------------------------------------------
// [0, 512)      bias (4 gates x 32 h floats)
// [1024, ...)   3 stage buffers; per stage: A 16KB + B 16KB = 32KB
// epilogue reuses [1024, 1024+73728): 4 planes of 128 x 36 floats
#define SM_STAGE(b) (1024 + (b) * 32768)
#define SMEM_TOTAL  (1024 + 3 * 32768)   // 99328
#define EP_BASE     1024
#define EP_PLANE    18432                // 128 * 36 * 4
#define EP_ROW      144                  // 36 floats

// ---------------- conversion kernels -----------------------------------------
// X + H activations to fp16, plus bias merge; grid-stride over float4 units.
__global__ void conv_acts_kernel(const float* __restrict__ X,
                                 const float* __restrict__ H,
                                 const float* __restrict__ bU,
                                 const float* __restrict__ bW,
                                 __half* __restrict__ Xh,
                                 __half* __restrict__ Hh) {
    const int n1 = BATCH * DIN / 4;
    const int n2 = BATCH * HH / 4;
    int i = blockIdx.x * blockDim.x + threadIdx.x;
    if (i < 2048) g_bias[i] = bU[i] + bW[i];
    for (; i < n1 + n2; i += gridDim.x * blockDim.x) {
        const float* src = (i < n1) ? X : H;
        __half* dst = (i < n1) ? Xh : Hh;
        int j = (i < n1) ? i : i - n1;
        float4 v = reinterpret_cast<const float4*>(src)[j];
        __half h[4] = {__float2half_rn(v.x), __float2half_rn(v.y),
                       __float2half_rn(v.z), __float2half_rn(v.w)};
        reinterpret_cast<uint2*>(dst)[j] = *reinterpret_cast<uint2*>(h);
    }
}

// Coalesced weight transpose: src [4, K, HH] f32 -> dst [4, HH, K] fp16.
// 32x32 smem tile; reads and writes both coalesced.
template<int K>
__global__ void conv_w_t_kernel(const float* __restrict__ src,
                                __half* __restrict__ dst) {
    __shared__ float tile[32][33];
    const int tx = threadIdx.x;          // 0..31
    const int ty = threadIdx.y;          // 0..7
    const int g  = blockIdx.z;
    const int k0 = blockIdx.y * 32;
    const int h0 = blockIdx.x * 32;
    #pragma unroll
    for (int j = 0; j < 4; j++)
        tile[ty + j * 8][tx] = src[((size_t)g * K + k0 + ty + j * 8) * HH + h0 + tx];
    __syncthreads();
    #pragma unroll
    for (int j = 0; j < 4; j++)
        dst[((size_t)g * HH + h0 + ty + j * 8) * K + k0 + tx] =
            __float2half_rn(tile[tx][ty + j * 8]);
}

// ---------------- stage source selection (compile-time foldable) -------------
__device__ __forceinline__ void stage_src(int s, const __half*& A,
                                          const __half*& Bt, int& K, int& k0) {
    if (s < 4) {
        K = DIN; k0 = s * BK;
        A = g_Xh; Bt = g_Ut;
    } else {
        K = HH; k0 = (s - 4) * BK;
        A = g_Hh; Bt = g_Wt;
    }
}

__device__ __forceinline__ void load_stage(uint32_t smem_base, int buf, int s,
                                           int bm0, int h0, int tid) {
    const __half *A, *Bt;
    int K, k0;
    stage_src(s, A, Bt, K, k0);
    uint32_t abase = smem_base + SM_STAGE(buf);
    // A tile: 128 rows x 64 k (128B/row), SW128
    #pragma unroll
    for (int i = 0; i < 4; i++) {
        int c = tid + i * 256;        // 0..1023 16B chunks
        int row = c >> 3, o = c & 7;
        cp16(abase + SW128(row * 128 + o * 16),
             A + (size_t)(bm0 + row) * K + k0 + o * 8);
    }
    // B tile: 128 rows (gate-major: row = g*32 + h_local) x 64 k
    uint32_t bbase = abase + 16384;
    #pragma unroll
    for (int i = 0; i < 4; i++) {
        int c = tid + i * 256;
        int row = c >> 3, o = c & 7;
        int g = row >> 5, hl = row & 31;
        cp16(bbase + SW128(row * 128 + o * 16),
             Bt + ((size_t)g * HH + h0 + hl) * K + k0 + o * 8);
    }
    CP_COMMIT();
}

// ---------------- main kernel -------------------------------------------------
__device__ __forceinline__ float sigmoid_f(float x) { return 1.0f / (1.0f + __expf(-x)); }
__device__ __forceinline__ float tanh_f(float x) {
    float ax = fabsf(x);
    float e = __expf(-2.0f * ax);
    float t = (1.0f - e) / (1.0f + e);
    return (x < 0.0f) ? -t : t;
}

__global__ void __launch_bounds__(256, 2)
lstm_mma_kernel(const float* __restrict__ Cin, float* __restrict__ out) {
    extern __shared__ char smem[];
    uint32_t smem_base = smem_u32(smem);
    float* bias_s = reinterpret_cast<float*>(smem);

    const int tid  = threadIdx.x;
    const int lane = tid & 31;
    const int w    = tid >> 5;
    const int wm   = (w >> 2) * 64;     // warp M offset
    const int nb   = (w & 3) * 32;      // warp N offset == gate*32
    const int h0   = blockIdx.x * 32;
    const int bm0  = blockIdx.y * BM;

    // prologue loads first (get TMA... cp.async traffic moving early)
    load_stage(smem_base, 0, 0, bm0, h0, tid);
    load_stage(smem_base, 1, 1, bm0, h0, tid);

    if (tid < 128)
        bias_s[tid] = g_bias[(tid >> 5) * HH + h0 + (tid & 31)];

    float acc[4][4][4];
    #pragma unroll
    for (int mi = 0; mi < 4; mi++)
        #pragma unroll
        for (int ni = 0; ni < 4; ni++)
            #pragma unroll
            for (int j = 0; j < 4; j++)
                acc[mi][ni][j] = 0.0f;

    // per-lane ldmatrix base offsets (bytes within tile, pre-swizzle)
    const int ar = wm + (lane & 15);
    const int aco = (lane >> 4) * 16;
    int offA[4];
    #pragma unroll
    for (int mi = 0; mi < 4; mi++)
        offA[mi] = (ar + mi * 16) * 128 + aco;
    const int grp = lane >> 3;
    const int br = nb + (grp >> 1) * 8 + (lane & 7);
    const int bco = (grp & 1) * 16;
    int offB[2];
    #pragma unroll
    for (int j = 0; j < 2; j++)
        offB[j] = (br + j * 16) * 128 + bco;

    // main loop: one __syncthreads per stage, load s+2 before compute s
    #pragma unroll
    for (int s = 0; s < NSTAGE; s++) {
        if (s + 1 < NSTAGE) CP_WAIT1(); else CP_WAIT0();
        __syncthreads();
        if (s + 2 < NSTAGE)
            load_stage(smem_base, (s + 2) % 3, s + 2, bm0, h0, tid);

        uint32_t ab = smem_base + SM_STAGE(s % 3);
        uint32_t bb = ab + 16384;
        #pragma unroll
        for (int ks = 0; ks < 4; ks++) {
            uint32_t a[4][4];
            #pragma unroll
            for (int mi = 0; mi < 4; mi++)
                LDSM_X4(a[mi][0], a[mi][1], a[mi][2], a[mi][3],
                        ab + SW128(offA[mi] + ks * 32));
            uint32_t b[2][4];
            #pragma unroll
            for (int j = 0; j < 2; j++)
                LDSM_X4(b[j][0], b[j][1], b[j][2], b[j][3],
                        bb + SW128(offB[j] + ks * 32));
            #pragma unroll
            for (int mi = 0; mi < 4; mi++)
                #pragma unroll
                for (int nt = 0; nt < 4; nt++)
                    mma16816(acc[mi][nt],
                             a[mi][0], a[mi][1], a[mi][2], a[mi][3],
                             b[nt >> 1][(nt & 1) * 2], b[nt >> 1][(nt & 1) * 2 + 1]);
        }
    }
    __syncthreads();   // all warps done with stage buffers before EP reuse

    // ---------------- epilogue ------------------------------------------------
    // 1) exchange gates via SMEM planes: Ep[g][m][h] (row stride 36 floats)
    {
        const int g = w & 3;
        char* ep = smem + EP_BASE + g * EP_PLANE;
        #pragma unroll
        for (int mi = 0; mi < 4; mi++) {
            #pragma unroll
            for (int nt = 0; nt < 4; nt++) {
                int row = wm + mi * 16 + (lane >> 2);
                int col = nt * 8 + (lane & 3) * 2;
                *reinterpret_cast<float2*>(ep + row * EP_ROW + col * 4) =
                    make_float2(acc[mi][nt][0], acc[mi][nt][1]);
                *reinterpret_cast<float2*>(ep + (row + 8) * EP_ROW + col * 4) =
                    make_float2(acc[mi][nt][2], acc[mi][nt][3]);
            }
        }
    }
    __syncthreads();

    // 2) LSTM update: thread t handles m = t/2, h = (t&1)*16 .. +16
    {
        const int m_loc = tid >> 1;
        const int hb = (tid & 1) * 16;
        const int m = bm0 + m_loc;
        const size_t BHo = (size_t)BATCH * HH;
        const char* ep = smem + EP_BASE;
        #pragma unroll
        for (int hq = 0; hq < 4; hq++) {
            const int h = hb + hq * 4;
            float4 gi = *reinterpret_cast<const float4*>(ep + 0 * EP_PLANE + m_loc * EP_ROW + h * 4);
            float4 gf = *reinterpret_cast<const float4*>(ep + 1 * EP_PLANE + m_loc * EP_ROW + h * 4);
            float4 go = *reinterpret_cast<const float4*>(ep + 2 * EP_PLANE + m_loc * EP_ROW + h * 4);
            float4 gc = *reinterpret_cast<const float4*>(ep + 3 * EP_PLANE + m_loc * EP_ROW + h * 4);
            float4 co = *reinterpret_cast<const float4*>(&Cin[(size_t)m * HH + h0 + h]);
            float vi[4] = {gi.x, gi.y, gi.z, gi.w};
            float vf[4] = {gf.x, gf.y, gf.z, gf.w};
            float vo[4] = {go.x, go.y, go.z, go.w};
            float vc[4] = {gc.x, gc.y, gc.z, gc.w};
            float vold[4] = {co.x, co.y, co.z, co.w};
            float hn[4], cn[4];
            #pragma unroll
            for (int j = 0; j < 4; j++) {
                int cj = h + j;
                float it = sigmoid_f(vi[j] + bias_s[0 * 32 + cj]);
                float ft = sigmoid_f(vf[j] + bias_s[1 * 32 + cj]);
                float ot = sigmoid_f(vo[j] + bias_s[2 * 32 + cj]);
                float ct = tanh_f(vc[j] + bias_s[3 * 32 + cj]);
                float c  = fmaf(it, ct, ft * vold[j]);
                cn[j] = c;
                hn[j] = ot * tanh_f(c);
            }
            *reinterpret_cast<float4*>(&out[(size_t)m * HH + h0 + h]) =
                make_float4(hn[0], hn[1], hn[2], hn[3]);
            *reinterpret_cast<float4*>(&out[BHo + (size_t)m * HH + h0 + h]) =
                make_float4(cn[0], cn[1], cn[2], cn[3]);
        }
    }
}

// ---------------- launch ------------------------------------------------------
extern "C" void kernel_launch(void* const* d_in, const int* in_sizes, int n_in,
                              void* d_out, int out_size) {
    const float* X   = (const float*)d_in[0];
    const float* Hin = (const float*)d_in[1];
    const float* Cin = (const float*)d_in[2];
    const float* U   = (const float*)d_in[3];
    const float* bU  = (const float*)d_in[4];
    const float* W   = (const float*)d_in[5];
    const float* bW  = (const float*)d_in[6];
    float* out = (float*)d_out;

    cudaFuncSetAttribute(lstm_mma_kernel,
                         cudaFuncAttributeMaxDynamicSharedMemorySize, SMEM_TOTAL);

    __half *xh, *hh, *ut, *wt;
    cudaGetSymbolAddress((void**)&xh, g_Xh);
    cudaGetSymbolAddress((void**)&hh, g_Hh);
    cudaGetSymbolAddress((void**)&ut, g_Ut);
    cudaGetSymbolAddress((void**)&wt, g_Wt);

    // pre-passes: activations+bias (1 kernel), weight transposes (2 kernels)
    conv_acts_kernel<<<8192, 256>>>(X, Hin, bU, bW, xh, hh);
    {
        dim3 blk(32, 8);
        dim3 gU(HH / 32, DIN / 32, 4);
        conv_w_t_kernel<DIN><<<gU, blk>>>(U, ut);
        dim3 gW(HH / 32, HH / 32, 4);
        conv_w_t_kernel<HH><<<gW, blk>>>(W, wt);
    }

    dim3 grid(HH / 32, BATCH / BM);   // (16, 512)
    lstm_mma_kernel<<<grid, 256, SMEM_TOTAL>>>(Cin, out);
}

// round 12
// speedup vs baseline: 1.0591x; 1.0591x over previous
#include <cuda_runtime.h>
#include <cuda_fp16.h>
#include <cstdint>

// ============================================================================
// LSTM cell via mma.sync fp16 single-pass (fp32 accum), fused LSTM epilogue.
// B=65536, Din=256, H=512 fixed.
// CTA: 256 batch x 128 cols (4 gates x 32 h). 8 warps (4M x 2N), warp 64x64
// -> LDSM bytes/MMA cut 192->128 (smem crossbar was the binding limit).
// K pipeline: BK=64, 3-buffer cp.async ring, 12 stages, round-6 two-sync
// structure (known good; the one-sync/full-unroll variant regressed).
// ============================================================================

#define BATCH 65536
#define DIN   256
#define HH    512
#define BM    256
#define BN    128
#define BK    64
#define NSTAGE 12

// ---------------- device scratch --------------------------------------------
__device__ __half g_Xh[BATCH * DIN];
__device__ __half g_Hh[BATCH * HH];
__device__ __half g_Ut[4 * HH * DIN];   // [g][h][k] K-major
__device__ __half g_Wt[4 * HH * HH];
__device__ float  g_bias[4 * HH];        // bU + bW

// ---------------- helpers ----------------------------------------------------
__device__ __forceinline__ uint32_t smem_u32(const void* p) {
    uint32_t a;
    asm("{ .reg .u64 t; cvta.to.shared.u64 t, %1; cvt.u32.u64 %0, t; }"
        : "=r"(a) : "l"(p));
    return a;
}
#define SW128(off) ((off) ^ (((off) >> 3) & 0x70))

__device__ __forceinline__ void cp16(uint32_t dst, const void* src) {
    asm volatile("cp.async.cg.shared.global [%0], [%1], 16;\n" :: "r"(dst), "l"(src));
}
#define CP_COMMIT() asm volatile("cp.async.commit_group;\n" ::: "memory")
#define CP_WAIT2()  asm volatile("cp.async.wait_group 2;\n" ::: "memory")
#define CP_WAIT1()  asm volatile("cp.async.wait_group 1;\n" ::: "memory")
#define CP_WAIT0()  asm volatile("cp.async.wait_group 0;\n" ::: "memory")

#define LDSM_X4(r0, r1, r2, r3, a)                                              \
    asm volatile("ldmatrix.sync.aligned.m8n8.x4.shared.b16 {%0,%1,%2,%3}, [%4];"\
        : "=r"(r0), "=r"(r1), "=r"(r2), "=r"(r3) : "r"(a))

__device__ __forceinline__ void mma16816(float* c, uint32_t a0, uint32_t a1,
                                         uint32_t a2, uint32_t a3,
                                         uint32_t b0, uint32_t b1) {
    asm volatile(
        "mma.sync.aligned.m16n8k16.row.col.f32.f16.f16.f32 "
        "{%0,%1,%2,%3}, {%4,%5,%6,%7}, {%8,%9}, {%0,%1,%2,%3};"
        : "+f"(c[0]), "+f"(c[1]), "+f"(c[2]), "+f"(c[3])
        : "r"(a0), "r"(a1), "r"(a2), "r"(a3), "r"(b0), "r"(b1));
}

// ---------------- SMEM layout ------------------------------------------------
// [0, 512)      bias (4 gates x 32 h floats)
// [1024, ...)   3 stage buffers; per stage: A 32KB (256x128B) + B 16KB
// epilogue reuses [1024, ...): 4 planes of 256 x 33 floats (stride 132B)
#define SM_STAGE(b) (1024 + (b) * 49152)
#define SMEM_TOTAL  (1024 + 3 * 49152)   // 148480
#define EP_BASE     1024
#define EP_PLANE    33792                // 256 * 33 * 4
#define EP_ROW      132                  // 33 floats

// ---------------- conversion kernels -----------------------------------------
__global__ void conv_acts_kernel(const float* __restrict__ X,
                                 const float* __restrict__ H,
                                 const float* __restrict__ bU,
                                 const float* __restrict__ bW,
                                 __half* __restrict__ Xh,
                                 __half* __restrict__ Hh) {
    const int n1 = BATCH * DIN / 4;
    const int n2 = BATCH * HH / 4;
    int i = blockIdx.x * blockDim.x + threadIdx.x;
    if (i < 2048) g_bias[i] = bU[i] + bW[i];
    for (; i < n1 + n2; i += gridDim.x * blockDim.x) {
        const float* src = (i < n1) ? X : H;
        __half* dst = (i < n1) ? Xh : Hh;
        int j = (i < n1) ? i : i - n1;
        float4 v = reinterpret_cast<const float4*>(src)[j];
        __half h[4] = {__float2half_rn(v.x), __float2half_rn(v.y),
                       __float2half_rn(v.z), __float2half_rn(v.w)};
        reinterpret_cast<uint2*>(dst)[j] = *reinterpret_cast<uint2*>(h);
    }
}

// Coalesced weight transpose: src [4, K, HH] f32 -> dst [4, HH, K] fp16.
template<int K>
__global__ void conv_w_t_kernel(const float* __restrict__ src,
                                __half* __restrict__ dst) {
    __shared__ float tile[32][33];
    const int tx = threadIdx.x;
    const int ty = threadIdx.y;
    const int g  = blockIdx.z;
    const int k0 = blockIdx.y * 32;
    const int h0 = blockIdx.x * 32;
    #pragma unroll
    for (int j = 0; j < 4; j++)
        tile[ty + j * 8][tx] = src[((size_t)g * K + k0 + ty + j * 8) * HH + h0 + tx];
    __syncthreads();
    #pragma unroll
    for (int j = 0; j < 4; j++)
        dst[((size_t)g * HH + h0 + ty + j * 8) * K + k0 + tx] =
            __float2half_rn(tile[tx][ty + j * 8]);
}

// ---------------- stage source selection -------------------------------------
__device__ __forceinline__ void stage_src(int s, const __half*& A,
                                          const __half*& Bt, int& K, int& k0) {
    if (s < 4) {
        K = DIN; k0 = s * BK;
        A = g_Xh; Bt = g_Ut;
    } else {
        K = HH; k0 = (s - 4) * BK;
        A = g_Hh; Bt = g_Wt;
    }
}

__device__ __forceinline__ void load_stage(uint32_t smem_base, int buf, int s,
                                           int bm0, int h0, int tid) {
    const __half *A, *Bt;
    int K, k0;
    stage_src(s, A, Bt, K, k0);
    uint32_t abase = smem_base + SM_STAGE(buf);
    // A tile: 256 rows x 64 k (128B/row), SW128 -> 2048 16B chunks
    #pragma unroll
    for (int i = 0; i < 8; i++) {
        int c = tid + i * 256;
        int row = c >> 3, o = c & 7;
        cp16(abase + SW128(row * 128 + o * 16),
             A + (size_t)(bm0 + row) * K + k0 + o * 8);
    }
    // B tile: 128 rows (gate-major: row = g*32 + h_local) x 64 k -> 1024 chunks
    uint32_t bbase = abase + 32768;
    #pragma unroll
    for (int i = 0; i < 4; i++) {
        int c = tid + i * 256;
        int row = c >> 3, o = c & 7;
        int g = row >> 5, hl = row & 31;
        cp16(bbase + SW128(row * 128 + o * 16),
             Bt + ((size_t)g * HH + h0 + hl) * K + k0 + o * 8);
    }
    CP_COMMIT();
}

// ---------------- main kernel -------------------------------------------------
__device__ __forceinline__ float sigmoid_f(float x) { return 1.0f / (1.0f + __expf(-x)); }
__device__ __forceinline__ float tanh_f(float x) {
    float ax = fabsf(x);
    float e = __expf(-2.0f * ax);
    float t = (1.0f - e) / (1.0f + e);
    return (x < 0.0f) ? -t : t;
}

__global__ void __launch_bounds__(256, 1)
lstm_mma_kernel(const float* __restrict__ Cin, float* __restrict__ out) {
    extern __shared__ char smem[];
    uint32_t smem_base = smem_u32(smem);
    float* bias_s = reinterpret_cast<float*>(smem);

    const int tid  = threadIdx.x;
    const int lane = tid & 31;
    const int w    = tid >> 5;
    const int wm   = (w >> 1) * 64;     // warp M offset (4 rows of warps)
    const int wn   = (w & 1) * 64;      // warp N offset (2 cols of warps)
    const int h0   = blockIdx.x * 32;
    const int bm0  = blockIdx.y * BM;

    // prologue loads
    load_stage(smem_base, 0, 0, bm0, h0, tid);
    load_stage(smem_base, 1, 1, bm0, h0, tid);
    load_stage(smem_base, 2, 2, bm0, h0, tid);

    if (tid < 128)
        bias_s[tid] = g_bias[(tid >> 5) * HH + h0 + (tid & 31)];

    // acc[m-tile 0..3][n-tile 0..7][4]
    float acc[4][8][4];
    #pragma unroll
    for (int mi = 0; mi < 4; mi++)
        #pragma unroll
        for (int nt = 0; nt < 8; nt++)
            #pragma unroll
            for (int j = 0; j < 4; j++)
                acc[mi][nt][j] = 0.0f;

    // per-lane ldmatrix base offsets (bytes within tile, pre-swizzle)
    const int ar = wm + (lane & 15);
    const int aco = (lane >> 4) * 16;
    int offA[4];
    #pragma unroll
    for (int mi = 0; mi < 4; mi++)
        offA[mi] = (ar + mi * 16) * 128 + aco;
    const int grp = lane >> 3;
    const int br = wn + (grp >> 1) * 8 + (lane & 7);
    const int bco = (grp & 1) * 16;
    int offB[4];
    #pragma unroll
    for (int j = 0; j < 4; j++)
        offB[j] = (br + j * 16) * 128 + bco;

    int buf = 0;
    for (int s = 0; s < NSTAGE; s++) {
        if (s + 2 < NSTAGE) CP_WAIT2();
        else if (s + 1 < NSTAGE) CP_WAIT1();
        else CP_WAIT0();
        __syncthreads();

        uint32_t ab = smem_base + SM_STAGE(buf);
        uint32_t bb = ab + 32768;
        #pragma unroll
        for (int ks = 0; ks < 4; ks++) {
            uint32_t a[4][4];
            #pragma unroll
            for (int mi = 0; mi < 4; mi++)
                LDSM_X4(a[mi][0], a[mi][1], a[mi][2], a[mi][3],
                        ab + SW128(offA[mi] + ks * 32));
            uint32_t b[4][4];
            #pragma unroll
            for (int j = 0; j < 4; j++)
                LDSM_X4(b[j][0], b[j][1], b[j][2], b[j][3],
                        bb + SW128(offB[j] + ks * 32));
            #pragma unroll
            for (int mi = 0; mi < 4; mi++)
                #pragma unroll
                for (int nt = 0; nt < 8; nt++)
                    mma16816(acc[mi][nt],
                             a[mi][0], a[mi][1], a[mi][2], a[mi][3],
                             b[nt >> 1][(nt & 1) * 2], b[nt >> 1][(nt & 1) * 2 + 1]);
        }
        __syncthreads();
        if (s + 3 < NSTAGE)
            load_stage(smem_base, buf, s + 3, bm0, h0, tid);
        buf = (buf == 2) ? 0 : buf + 1;
    }

    // ---------------- epilogue ------------------------------------------------
    // 1) exchange gates via SMEM planes: Ep[g][m][h], row stride 33 floats
    //    (bank-conflict-free reads: bank = (33m + h) % 32 = (m + h) % 32)
    {
        #pragma unroll
        for (int mi = 0; mi < 4; mi++) {
            #pragma unroll
            for (int nt = 0; nt < 8; nt++) {
                int ncol = wn + nt * 8 + (lane & 3) * 2;
                int g = ncol >> 5;
                int h = ncol & 31;
                char* ep = smem + EP_BASE + g * EP_PLANE;
                int r0 = wm + mi * 16 + (lane >> 2);
                *reinterpret_cast<float*>(ep + r0 * EP_ROW + h * 4)       = acc[mi][nt][0];
                *reinterpret_cast<float*>(ep + r0 * EP_ROW + (h + 1) * 4) = acc[mi][nt][1];
                *reinterpret_cast<float*>(ep + (r0 + 8) * EP_ROW + h * 4)       = acc[mi][nt][2];
                *reinterpret_cast<float*>(ep + (r0 + 8) * EP_ROW + (h + 1) * 4) = acc[mi][nt][3];
            }
        }
    }
    __syncthreads();

    // 2) LSTM update: thread t handles row m = bm0 + t, all 32 h columns
    {
        const int m_loc = tid;
        const int m = bm0 + m_loc;
        const size_t BHo = (size_t)BATCH * HH;
        const char* ep = smem + EP_BASE;
        #pragma unroll
        for (int hq = 0; hq < 8; hq++) {
            const int h = hq * 4;
            float vi[4], vf[4], vo[4], vc[4];
            #pragma unroll
            for (int j = 0; j < 4; j++) {
                vi[j] = *reinterpret_cast<const float*>(ep + 0 * EP_PLANE + m_loc * EP_ROW + (h + j) * 4);
                vf[j] = *reinterpret_cast<const float*>(ep + 1 * EP_PLANE + m_loc * EP_ROW + (h + j) * 4);
                vo[j] = *reinterpret_cast<const float*>(ep + 2 * EP_PLANE + m_loc * EP_ROW + (h + j) * 4);
                vc[j] = *reinterpret_cast<const float*>(ep + 3 * EP_PLANE + m_loc * EP_ROW + (h + j) * 4);
            }
            float4 co = *reinterpret_cast<const float4*>(&Cin[(size_t)m * HH + h0 + h]);
            float vold[4] = {co.x, co.y, co.z, co.w};
            float hn[4], cn[4];
            #pragma unroll
            for (int j = 0; j < 4; j++) {
                int cj = h + j;
                float it = sigmoid_f(vi[j] + bias_s[0 * 32 + cj]);
                float ft = sigmoid_f(vf[j] + bias_s[1 * 32 + cj]);
                float ot = sigmoid_f(vo[j] + bias_s[2 * 32 + cj]);
                float ct = tanh_f(vc[j] + bias_s[3 * 32 + cj]);
                float c  = fmaf(it, ct, ft * vold[j]);
                cn[j] = c;
                hn[j] = ot * tanh_f(c);
            }
            *reinterpret_cast<float4*>(&out[(size_t)m * HH + h0 + h]) =
                make_float4(hn[0], hn[1], hn[2], hn[3]);
            *reinterpret_cast<float4*>(&out[BHo + (size_t)m * HH + h0 + h]) =
                make_float4(cn[0], cn[1], cn[2], cn[3]);
        }
    }
}

// ---------------- launch ------------------------------------------------------
extern "C" void kernel_launch(void* const* d_in, const int* in_sizes, int n_in,
                              void* d_out, int out_size) {
    const float* X   = (const float*)d_in[0];
    const float* Hin = (const float*)d_in[1];
    const float* Cin = (const float*)d_in[2];
    const float* U   = (const float*)d_in[3];
    const float* bU  = (const float*)d_in[4];
    const float* W   = (const float*)d_in[5];
    const float* bW  = (const float*)d_in[6];
    float* out = (float*)d_out;

    cudaFuncSetAttribute(lstm_mma_kernel,
                         cudaFuncAttributeMaxDynamicSharedMemorySize, SMEM_TOTAL);

    __half *xh, *hh, *ut, *wt;
    cudaGetSymbolAddress((void**)&xh, g_Xh);
    cudaGetSymbolAddress((void**)&hh, g_Hh);
    cudaGetSymbolAddress((void**)&ut, g_Ut);
    cudaGetSymbolAddress((void**)&wt, g_Wt);

    conv_acts_kernel<<<8192, 256>>>(X, Hin, bU, bW, xh, hh);
    {
        dim3 blk(32, 8);
        dim3 gU(HH / 32, DIN / 32, 4);
        conv_w_t_kernel<DIN><<<gU, blk>>>(U, ut);
        dim3 gW(HH / 32, HH / 32, 4);
        conv_w_t_kernel<HH><<<gW, blk>>>(W, wt);
    }

    dim3 grid(HH / 32, BATCH / BM);   // (16, 256)
    lstm_mma_kernel<<<grid, 256, SMEM_TOTAL>>>(Cin, out);
}